// round 7
// baseline (speedup 1.0000x reference)
#include <cuda_runtime.h>
#include <cuda_bf16.h>
#include <cuda_fp8.h>
#include <cstdint>

typedef __nv_bfloat16 bf16;

// Problem constants: B=4, S=4096, HID=2048, H=16, P=256, D=128, N=16
#define NELEM 33554432u   // 4*4096*2048
#define MDIM 16384
#define NDIM 2048
#define NCH2 32           // chunks per pass (K bytes 4096 / 128)

// paged bf16 hi/lo buffers: [page=(b*16+head)*16+n][256][128]
__device__ bf16 g_qhi[NELEM];
__device__ bf16 g_qlo[NELEM];
__device__ bf16 g_khi[NELEM];
__device__ bf16 g_klo[NELEM];
__device__ bf16 g_vthi[NELEM];  // transposed: [page][d2:128][p2:256]
__device__ bf16 g_vtlo[NELEM];

// GEMM operand buffers
__device__ bf16 g_hbf[(size_t)MDIM * 2048];           // bf16 hi of hidden
__device__ unsigned char g_h8[(size_t)MDIM * 4096];   // [Ahi8 | Alo8*512]
__device__ bf16 g_cbf[(size_t)MDIM * 2048];           // bf16 hi of ctx
__device__ unsigned char g_c8[(size_t)MDIM * 4096];
__device__ bf16 g_wqbf[(size_t)NDIM * 2048];
__device__ bf16 g_wkbf[(size_t)NDIM * 2048];
__device__ bf16 g_wvbf[(size_t)NDIM * 2048];
__device__ bf16 g_wobf[(size_t)NDIM * 2048];
__device__ unsigned char g_wq8[(size_t)NDIM * 4096];  // [Wlo8*8192 | Whi8*16]
__device__ unsigned char g_wk8[(size_t)NDIM * 4096];
__device__ unsigned char g_wv8[(size_t)NDIM * 4096];
__device__ unsigned char g_wo8[(size_t)NDIM * 4096];

// ---------------------------------------------------------------------------
// helpers
// ---------------------------------------------------------------------------
__device__ __forceinline__ uint32_t smem_u32(const void* p) {
    uint32_t a;
    asm("{ .reg .u64 t; cvta.to.shared.u64 t, %1; cvt.u32.u64 %0, t; }"
        : "=r"(a) : "l"(p));
    return a;
}
__device__ __forceinline__ void cp16(uint32_t sa, const void* g) {
    asm volatile("cp.async.cg.shared.global [%0], [%1], 16;" :: "r"(sa), "l"(g));
}
#define CP_COMMIT() asm volatile("cp.async.commit_group;" ::: "memory")

__device__ __forceinline__ void ldsm4(uint32_t* r, uint32_t addr) {
    asm volatile("ldmatrix.sync.aligned.m8n8.x4.shared.b16 {%0,%1,%2,%3}, [%4];"
                 : "=r"(r[0]), "=r"(r[1]), "=r"(r[2]), "=r"(r[3]) : "r"(addr));
}
__device__ __forceinline__ void mma16816(float* c, const uint32_t* a,
                                         const uint32_t* b) {
    asm volatile(
        "mma.sync.aligned.m16n8k16.row.col.f32.bf16.bf16.f32 "
        "{%0,%1,%2,%3}, {%4,%5,%6,%7}, {%8,%9}, {%0,%1,%2,%3};"
        : "+f"(c[0]), "+f"(c[1]), "+f"(c[2]), "+f"(c[3])
        : "r"(a[0]), "r"(a[1]), "r"(a[2]), "r"(a[3]), "r"(b[0]), "r"(b[1]));
}
__device__ __forceinline__ void mma_e4m3(float* c, const uint32_t* a,
                                         const uint32_t* b) {
    asm volatile(
        "mma.sync.aligned.m16n8k32.row.col.f32.e4m3.e4m3.f32 "
        "{%0,%1,%2,%3}, {%4,%5,%6,%7}, {%8,%9}, {%0,%1,%2,%3};"
        : "+f"(c[0]), "+f"(c[1]), "+f"(c[2]), "+f"(c[3])
        : "r"(a[0]), "r"(a[1]), "r"(a[2]), "r"(a[3]), "r"(b[0]), "r"(b[1]));
}
__device__ __forceinline__ uint32_t swz(uint32_t o) { return o ^ ((o >> 3) & 0x70); }
__device__ __forceinline__ uint32_t pack2(bf16 a, bf16 b) {
    return (uint32_t)*(uint16_t*)&a | ((uint32_t)*(uint16_t*)&b << 16);
}
__device__ __forceinline__ unsigned char e4m3(float x) {
    return (unsigned char)__nv_cvt_float_to_fp8(x, __NV_SATFINITE, __NV_E4M3);
}

// ---------------------------------------------------------------------------
// operand prep
// ---------------------------------------------------------------------------
__global__ __launch_bounds__(256)
void make_act(const float* __restrict__ src, bf16* __restrict__ abf,
              unsigned char* __restrict__ a8) {
    size_t t = (size_t)blockIdx.x * 256 + threadIdx.x;
    size_t row = t >> 9;
    int col = (int)(t & 511) << 2;
    float4 x = *(const float4*)(src + row * 2048 + col);
    float xs[4] = {x.x, x.y, x.z, x.w};
    bf16 h[4];
    unsigned char hi8[4], lo8[4];
#pragma unroll
    for (int i = 0; i < 4; i++) {
        h[i] = __float2bfloat16(xs[i]);
        float hf = __bfloat162float(h[i]);
        hi8[i] = e4m3(hf);
        lo8[i] = e4m3(512.f * (xs[i] - hf));
    }
    bf16* d = abf + row * 2048 + col;
    ((uint32_t*)d)[0] = pack2(h[0], h[1]);
    ((uint32_t*)d)[1] = pack2(h[2], h[3]);
    *(uint32_t*)(a8 + row * 4096 + col) = *(uint32_t*)hi8;
    *(uint32_t*)(a8 + row * 4096 + 2048 + col) = *(uint32_t*)lo8;
}

__global__ __launch_bounds__(256)
void make_wt(const float* __restrict__ src, bf16* __restrict__ wbf,
             unsigned char* __restrict__ w8) {
    size_t t = (size_t)blockIdx.x * 256 + threadIdx.x;
    size_t row = t >> 9;
    int col = (int)(t & 511) << 2;
    float4 x = *(const float4*)(src + row * 2048 + col);
    float xs[4] = {x.x, x.y, x.z, x.w};
    bf16 h[4];
    unsigned char hi8[4], lo8[4];
#pragma unroll
    for (int i = 0; i < 4; i++) {
        h[i] = __float2bfloat16(xs[i]);
        float hf = __bfloat162float(h[i]);
        hi8[i] = e4m3(16.f * hf);
        lo8[i] = e4m3(8192.f * (xs[i] - hf));
    }
    bf16* d = wbf + row * 2048 + col;
    ((uint32_t*)d)[0] = pack2(h[0], h[1]);
    ((uint32_t*)d)[1] = pack2(h[2], h[3]);
    *(uint32_t*)(w8 + row * 4096 + col) = *(uint32_t*)lo8;        // Wlo8 first
    *(uint32_t*)(w8 + row * 4096 + 2048 + col) = *(uint32_t*)hi8; // Whi8 second
}

// ---------------------------------------------------------------------------
// GEMM mainloop pass (templated on mma type). Block 128m x 256n. Operands are
// byte pointers with row stride 4096B; K covered in 32 chunks of 128B.
// 4-stage cp.async ring, single __syncthreads per chunk.
// ---------------------------------------------------------------------------
#define NSTG 4
#define STG_BYTES 49152   // A 16KB + B 32KB
#define GEMM_SMEM (NSTG * STG_BYTES)

__device__ __forceinline__ void load_chunk2(
    const char* __restrict__ A, const char* __restrict__ W,
    uint32_t stg, int chunk, int tid) {
#pragma unroll
    for (int j = 0; j < 12; j++) {
        int idx = j * 256 + tid;
        int row = idx >> 3;
        int c16 = idx & 7;
        bool isB = row >= 128;
        int r = isB ? row - 128 : row;
        const char* src = (isB ? W : A) + (size_t)r * 4096 + chunk * 128 + c16 * 16;
        uint32_t off = swz((uint32_t)(r * 128 + c16 * 16));
        cp16(stg + (isB ? 16384 : 0) + off, src);
    }
    CP_COMMIT();
}

template <int FP8>
__device__ __forceinline__ void mainloop2(
    const char* __restrict__ A, const char* __restrict__ W,
    uint32_t data, float (&acc)[4][8][4], int tid, int wid, int lane) {
    const int m_base = (wid & 1) * 64;
    const int n_base = (wid >> 1) * 64;

#pragma unroll
    for (int c = 0; c < NSTG - 1; c++)
        load_chunk2(A, W, data + c * STG_BYTES, c, tid);

    const int raL = lane & 15;
    const int akh = lane >> 4;
    const int rbL = (lane & 7) + ((lane & 16) >> 1);
    const int bkh = (lane >> 3) & 1;

    for (int i = 0; i < NCH2; i++) {
        int pend = NCH2 - 1 - i; if (pend > NSTG - 2) pend = NSTG - 2;
        if (pend == 2)      asm volatile("cp.async.wait_group 2;" ::: "memory");
        else if (pend == 1) asm volatile("cp.async.wait_group 1;" ::: "memory");
        else                asm volatile("cp.async.wait_group 0;" ::: "memory");
        __syncthreads();

        int nc = i + NSTG - 1;
        if (nc < NCH2)
            load_chunk2(A, W, data + (nc & 3) * STG_BYTES, nc, tid);

        uint32_t sA = data + (i & 3) * STG_BYTES;
        uint32_t sB = sA + 16384;

#pragma unroll
        for (int ks = 0; ks < 4; ks++) {
            uint32_t a[4][4];
#pragma unroll
            for (int mt = 0; mt < 4; mt++) {
                int ra = m_base + mt * 16 + raL;
                uint32_t ck = (uint32_t)(ks * 2 + akh) ^ (uint32_t)(ra & 7);
                ldsm4(a[mt], sA + (uint32_t)(ra * 128) + (ck << 4));
            }
            uint32_t b[4][4];
#pragma unroll
            for (int nt2 = 0; nt2 < 4; nt2++) {
                int rb = n_base + nt2 * 16 + rbL;
                uint32_t ck = (uint32_t)(ks * 2 + bkh) ^ (uint32_t)(rb & 7);
                ldsm4(b[nt2], sB + (uint32_t)(rb * 128) + (ck << 4));
            }
#pragma unroll
            for (int mt = 0; mt < 4; mt++)
#pragma unroll
                for (int nt = 0; nt < 8; nt++) {
                    if (FP8)
                        mma_e4m3(acc[mt][nt], a[mt], &b[nt >> 1][(nt & 1) * 2]);
                    else
                        mma16816(acc[mt][nt], a[mt], &b[nt >> 1][(nt & 1) * 2]);
                }
        }
    }
    __syncthreads();
}

// ---------------------------------------------------------------------------
// Merged QKV GEMM. grid (24, 128): wsel = x>>3 selects weight, bn=(x&7)*256.
// fp8 correction pass, scale, bf16 hi pass, then paged epilogues.
// ---------------------------------------------------------------------------
__global__ __launch_bounds__(256, 1)
void gemm_qkv(const bf16* __restrict__ Abf, const unsigned char* __restrict__ A8,
              const bf16* __restrict__ Wb0, const bf16* __restrict__ Wb1,
              const bf16* __restrict__ Wb2,
              const unsigned char* __restrict__ W80,
              const unsigned char* __restrict__ W81,
              const unsigned char* __restrict__ W82,
              const float* __restrict__ b0, const float* __restrict__ b1,
              const float* __restrict__ b2,
              bf16* __restrict__ qhi, bf16* __restrict__ qlo,
              bf16* __restrict__ khi, bf16* __restrict__ klo,
              bf16* __restrict__ vthi, bf16* __restrict__ vtlo) {
    extern __shared__ char dsm[];
    const uint32_t data = smem_u32(dsm);
    const int tid = threadIdx.x, wid = tid >> 5, lane = tid & 31;
    const int wsel = blockIdx.x >> 3;
    const int bn = (blockIdx.x & 7) << 8;
    const int bm = blockIdx.y << 7;
    const bf16* Wbf = wsel == 0 ? Wb0 : wsel == 1 ? Wb1 : Wb2;
    const unsigned char* W8 = wsel == 0 ? W80 : wsel == 1 ? W81 : W82;
    const float* bias = wsel == 0 ? b0 : wsel == 1 ? b1 : b2;

    float acc[4][8][4];
#pragma unroll
    for (int mt = 0; mt < 4; mt++)
#pragma unroll
        for (int nt = 0; nt < 8; nt++)
#pragma unroll
            for (int r = 0; r < 4; r++) acc[mt][nt][r] = 0.f;

    // fp8 correction pass
    mainloop2<1>((const char*)(A8 + (size_t)bm * 4096),
                 (const char*)(W8 + (size_t)bn * 4096), data, acc, tid, wid, lane);
    const float s = 1.f / 8192.f;
#pragma unroll
    for (int mt = 0; mt < 4; mt++)
#pragma unroll
        for (int nt = 0; nt < 8; nt++)
#pragma unroll
            for (int r = 0; r < 4; r++) acc[mt][nt][r] *= s;
    // bf16 hi*hi pass
    mainloop2<0>((const char*)(Abf + (size_t)bm * 2048),
                 (const char*)(Wbf + (size_t)bn * 2048), data, acc, tid, wid, lane);

    const int m_base = (wid & 1) * 64;
    const int n_base = (wid >> 1) * 64;

    // bias add
#pragma unroll
    for (int mt = 0; mt < 4; mt++)
#pragma unroll
        for (int nt = 0; nt < 8; nt++) {
            int col = bn + n_base + nt * 8 + (lane & 3) * 2;
            float bb0 = bias[col], bb1 = bias[col + 1];
            acc[mt][nt][0] += bb0; acc[mt][nt][1] += bb1;
            acc[mt][nt][2] += bb0; acc[mt][nt][3] += bb1;
        }

    const int b = bm >> 12, s0 = bm & 4095;
    const int page = s0 >> 8, par = (s0 >> 7) & 1;

    if (wsel < 2) {
        bf16* dhi = wsel ? khi : qhi;
        bf16* dlo = wsel ? klo : qlo;
        float* smf = (float*)dsm;  // [c:128][r:132]
#pragma unroll 1
        for (int hh = 0; hh < 2; hh++) {
            if ((wid >> 2) == hh) {
                int cbase = n_base - hh * 128;
#pragma unroll
                for (int mt = 0; mt < 4; mt++) {
                    int r = m_base + mt * 16 + (lane >> 2);
#pragma unroll
                    for (int nt = 0; nt < 8; nt++) {
                        int c = cbase + nt * 8 + (lane & 3) * 2;
                        smf[c * 132 + r] = acc[mt][nt][0];
                        smf[(c + 1) * 132 + r] = acc[mt][nt][1];
                        smf[c * 132 + r + 8] = acc[mt][nt][2];
                        smf[(c + 1) * 132 + r + 8] = acc[mt][nt][3];
                    }
                }
            }
            __syncthreads();
            int head = (bn >> 7) + hh;
            size_t pb = ((size_t)((b * 16 + head) * 16 + page)) << 15;
            for (int cc = wid; cc < 128; cc += 8) {
                float4 v = *(const float4*)&smf[cc * 132 + lane * 4];
                bf16 h0 = __float2bfloat16(v.x), h1 = __float2bfloat16(v.y);
                bf16 h2 = __float2bfloat16(v.z), h3 = __float2bfloat16(v.w);
                bf16 l0 = __float2bfloat16(v.x - __bfloat162float(h0));
                bf16 l1 = __float2bfloat16(v.y - __bfloat162float(h1));
                bf16 l2 = __float2bfloat16(v.z - __bfloat162float(h2));
                bf16 l3 = __float2bfloat16(v.w - __bfloat162float(h3));
                size_t off = pb + (size_t)(2 * cc + par) * 128 + lane * 4;
                *(uint2*)(dhi + off) = make_uint2(pack2(h0, h1), pack2(h2, h3));
                *(uint2*)(dlo + off) = make_uint2(pack2(l0, l1), pack2(l2, l3));
            }
            __syncthreads();
        }
    } else {
        // V: transposed paged store [page][d2][p2]
#pragma unroll
        for (int nt = 0; nt < 8; nt++) {
            int nl = n_base + nt * 8 + (lane & 3) * 2;
            int hh = nl >> 7;
            int cw = nl & 127;
            int head = (bn >> 7) + hh;
            size_t pb = ((size_t)((b * 16 + head) * 16 + page)) << 15;
#pragma unroll
            for (int mt = 0; mt < 4; mt++) {
                int r0 = m_base + mt * 16 + (lane >> 2);
#pragma unroll
                for (int q = 0; q < 2; q++) {
                    int r = r0 + q * 8;
#pragma unroll
                    for (int e = 0; e < 2; e++) {
                        float v = acc[mt][nt][q * 2 + e];
                        bf16 h = __float2bfloat16(v);
                        bf16 l = __float2bfloat16(v - __bfloat162float(h));
                        size_t off = pb + (size_t)r * 256 + 2 * (cw + e) + par;
                        vthi[off] = h;
                        vtlo[off] = l;
                    }
                }
            }
        }
    }
}

// ---------------------------------------------------------------------------
// Wo GEMM: plain fp32 output
// ---------------------------------------------------------------------------
__global__ __launch_bounds__(256, 1)
void gemm_wo(const bf16* __restrict__ Abf, const unsigned char* __restrict__ A8,
             const bf16* __restrict__ Wbf, const unsigned char* __restrict__ W8,
             const float* __restrict__ bias, float* __restrict__ C) {
    extern __shared__ char dsm[];
    const uint32_t data = smem_u32(dsm);
    const int tid = threadIdx.x, wid = tid >> 5, lane = tid & 31;
    const int bn = blockIdx.x << 8, bm = blockIdx.y << 7;

    float acc[4][8][4];
#pragma unroll
    for (int mt = 0; mt < 4; mt++)
#pragma unroll
        for (int nt = 0; nt < 8; nt++)
#pragma unroll
            for (int r = 0; r < 4; r++) acc[mt][nt][r] = 0.f;

    mainloop2<1>((const char*)(A8 + (size_t)bm * 4096),
                 (const char*)(W8 + (size_t)bn * 4096), data, acc, tid, wid, lane);
    const float s = 1.f / 8192.f;
#pragma unroll
    for (int mt = 0; mt < 4; mt++)
#pragma unroll
        for (int nt = 0; nt < 8; nt++)
#pragma unroll
            for (int r = 0; r < 4; r++) acc[mt][nt][r] *= s;
    mainloop2<0>((const char*)(Abf + (size_t)bm * 2048),
                 (const char*)(Wbf + (size_t)bn * 2048), data, acc, tid, wid, lane);

    const int m_base = (wid & 1) * 64;
    const int n_base = (wid >> 1) * 64;
#pragma unroll
    for (int mt = 0; mt < 4; mt++) {
        int r0 = bm + m_base + mt * 16 + (lane >> 2);
#pragma unroll
        for (int nt = 0; nt < 8; nt++) {
            int col = bn + n_base + nt * 8 + (lane & 3) * 2;
            float bb0 = bias[col], bb1 = bias[col + 1];
            float* p0 = C + (size_t)r0 * NDIM + col;
            float* p1 = p0 + (size_t)8 * NDIM;
            *(float2*)p0 = make_float2(acc[mt][nt][0] + bb0, acc[mt][nt][1] + bb1);
            *(float2*)p1 = make_float2(acc[mt][nt][2] + bb0, acc[mt][nt][3] + bb1);
        }
    }
}

// ---------------------------------------------------------------------------
// HMMA attention. Block = (qt 0..3, h2 0..15, x2 0..63), 256 threads.
// ---------------------------------------------------------------------------
#define ATT_SQ 0
#define ATT_SK 32768
#define ATT_SP 32768
#define ATT_SV 98304
#define ATT_SS 163840
#define ATT_SMEM 230400
#define SST 260

__global__ __launch_bounds__(256, 1)
void attn2(const bf16* __restrict__ qhi, const bf16* __restrict__ qlo,
           const bf16* __restrict__ khi, const bf16* __restrict__ klo,
           const bf16* __restrict__ vthi, const bf16* __restrict__ vtlo,
           bf16* __restrict__ cbf, unsigned char* __restrict__ c8) {
    extern __shared__ char smraw[];
    const uint32_t sb = smem_u32(smraw);
    float* sS = (float*)(smraw + ATT_SS);

    const float SCALE = 0.08838834764831843f;
    const int qt = blockIdx.x, h2 = blockIdx.y, x2 = blockIdx.z;
    const int tid = threadIdx.x, wid = tid >> 5, lane = tid & 31;
    const size_t pagebase = ((size_t)(x2 * 16 + h2)) << 15;

    const int raL = lane & 15, akh = lane >> 4;
    const int rbL = (lane & 7) + ((lane & 16) >> 1), bkh = (lane >> 3) & 1;

    // Phase 1 loads: Q (64 rows) + K (256 rows), hi & lo
#pragma unroll
    for (int q = 0; q < 8; q++) {
        int idx = q * 256 + tid;
        int prec = idx >> 10, rem = idx & 1023;
        int r = rem >> 4, kc = (rem >> 3) & 1, c16 = rem & 7;
        const bf16* s = (prec ? qlo : qhi) + pagebase +
                        (size_t)(qt * 64 + r) * 128 + kc * 64 + c16 * 8;
        cp16(sb + ATT_SQ + prec * 16384 + kc * 8192 + swz(r * 128 + c16 * 16), s);
    }
#pragma unroll
    for (int q = 0; q < 32; q++) {
        int idx = q * 256 + tid;
        int prec = idx >> 12, rem = idx & 4095;
        int r = rem >> 4, kc = (rem >> 3) & 1, c16 = rem & 7;
        const bf16* s = (prec ? klo : khi) + pagebase + (size_t)r * 128 +
                        kc * 64 + c16 * 8;
        cp16(sb + ATT_SK + prec * 65536 + kc * 32768 + swz(r * 128 + c16 * 16), s);
    }
    CP_COMMIT();
    asm volatile("cp.async.wait_group 0;" ::: "memory");
    __syncthreads();

    // QK: S[64][256] = 3-term split. warp tile 32m x 64n
    {
        const int m_base = (wid & 1) * 32;
        const int n_base = (wid >> 1) * 64;
        float acc[2][8][4];
#pragma unroll
        for (int mt = 0; mt < 2; mt++)
#pragma unroll
            for (int nt = 0; nt < 8; nt++)
#pragma unroll
                for (int r = 0; r < 4; r++) acc[mt][nt][r] = 0.f;

        const int ap[3] = {0, 0, 1}, bp[3] = {0, 1, 0};
#pragma unroll 1
        for (int t = 0; t < 3; t++) {
            uint32_t Ab = sb + ATT_SQ + ap[t] * 16384;
            uint32_t Bb = sb + ATT_SK + bp[t] * 65536;
#pragma unroll
            for (int kc = 0; kc < 2; kc++) {
#pragma unroll
                for (int ks = 0; ks < 4; ks++) {
                    uint32_t a[2][4];
#pragma unroll
                    for (int mt = 0; mt < 2; mt++) {
                        int ra = m_base + mt * 16 + raL;
                        uint32_t ck = (uint32_t)(ks * 2 + akh) ^ (uint32_t)(ra & 7);
                        ldsm4(a[mt], Ab + kc * 8192 + (uint32_t)(ra * 128) + (ck << 4));
                    }
                    uint32_t bfr[4][4];
#pragma unroll
                    for (int nt2 = 0; nt2 < 4; nt2++) {
                        int rb = n_base + nt2 * 16 + rbL;
                        uint32_t ck = (uint32_t)(ks * 2 + bkh) ^ (uint32_t)(rb & 7);
                        ldsm4(bfr[nt2], Bb + kc * 32768 + (uint32_t)(rb * 128) + (ck << 4));
                    }
#pragma unroll
                    for (int mt = 0; mt < 2; mt++)
#pragma unroll
                        for (int nt = 0; nt < 8; nt++)
                            mma16816(acc[mt][nt], a[mt], &bfr[nt >> 1][(nt & 1) * 2]);
                }
            }
        }
#pragma unroll
        for (int mt = 0; mt < 2; mt++) {
            int r = m_base + mt * 16 + (lane >> 2);
#pragma unroll
            for (int nt = 0; nt < 8; nt++) {
                int c = n_base + nt * 8 + (lane & 3) * 2;
                sS[r * SST + c] = acc[mt][nt][0] * SCALE;
                sS[r * SST + c + 1] = acc[mt][nt][1] * SCALE;
                sS[(r + 8) * SST + c] = acc[mt][nt][2] * SCALE;
                sS[(r + 8) * SST + c + 1] = acc[mt][nt][3] * SCALE;
            }
        }
    }
    __syncthreads();

    // prefetch V chunks 0 (Vhi kt0) and 1 (Vlo kt0)
#pragma unroll
    for (int cch = 0; cch < 2; cch++) {
        const bf16* base = (cch ? vtlo : vthi) + pagebase;
#pragma unroll
        for (int q = 0; q < 4; q++) {
            int idx = q * 256 + tid;
            int r = idx >> 3, c16 = idx & 7;
            cp16(sb + ATT_SV + cch * 16384 + swz(r * 128 + c16 * 16),
                 base + (size_t)r * 256 + 0 * 64 + c16 * 8);
        }
        CP_COMMIT();
    }

    // softmax: warp per row
    for (int r = wid; r < 64; r += 8) {
        float v[8];
        float m = -3.4e38f;
#pragma unroll
        for (int c = 0; c < 8; c++) {
            v[c] = sS[r * SST + 32 * c + lane];
            m = fmaxf(m, v[c]);
        }
#pragma unroll
        for (int o = 16; o; o >>= 1) m = fmaxf(m, __shfl_xor_sync(0xffffffffu, m, o));
        float sum = 0.f;
#pragma unroll
        for (int c = 0; c < 8; c++) {
            v[c] = __expf(v[c] - m);
            sum += v[c];
        }
#pragma unroll
        for (int o = 16; o; o >>= 1) sum += __shfl_xor_sync(0xffffffffu, sum, o);
        float inv = 1.0f / sum;
#pragma unroll
        for (int c = 0; c < 8; c++) sS[r * SST + 32 * c + lane] = v[c] * inv;
    }
    __syncthreads();

    // P convert: S fp32 -> P hi/lo bf16 sub-tiles [prec][kc4][64][128B]
    {
        int m = tid >> 2, kcq = tid & 3;
        const float* srow = sS + m * SST + kcq * 64;
        uint32_t dh = ATT_SP + kcq * 8192;
#pragma unroll
        for (int j = 0; j < 32; j++) {
            float s0 = srow[2 * j], s1 = srow[2 * j + 1];
            bf16 h0 = __float2bfloat16(s0), h1 = __float2bfloat16(s1);
            bf16 l0 = __float2bfloat16(s0 - __bfloat162float(h0));
            bf16 l1 = __float2bfloat16(s1 - __bfloat162float(h1));
            uint32_t off = swz((uint32_t)(m * 128 + 4 * j));
            *(uint32_t*)(smraw + dh + off) = pack2(h0, h1);
            *(uint32_t*)(smraw + dh + 32768 + off) = pack2(l0, l1);
        }
    }
    __syncthreads();

    // PV: ctx[64][128] = 3-term split, V streamed in 8 chunks.
    float acc2[2][4][4];
#pragma unroll
    for (int mt = 0; mt < 2; mt++)
#pragma unroll
        for (int nt = 0; nt < 4; nt++)
#pragma unroll
            for (int r = 0; r < 4; r++) acc2[mt][nt][r] = 0.f;

    const int m2 = (wid & 1) * 32;
    const int n2 = (wid >> 1) * 32;

#pragma unroll 1
    for (int j = 0; j < 8; j++) {
        int kt = j >> 1, vp = j & 1;
        if (j < 7) asm volatile("cp.async.wait_group 1;" ::: "memory");
        else       asm volatile("cp.async.wait_group 0;" ::: "memory");
        __syncthreads();

        uint32_t Vb = sb + ATT_SV + (j & 1) * 16384;
        int npass = vp ? 1 : 2;
#pragma unroll 1
        for (int p = 0; p < npass; p++) {
            int pp = vp ? 0 : p;
            uint32_t Pb = sb + ATT_SP + pp * 32768 + kt * 8192;
#pragma unroll
            for (int ks = 0; ks < 4; ks++) {
                uint32_t a[2][4];
#pragma unroll
                for (int mt = 0; mt < 2; mt++) {
                    int ra = m2 + mt * 16 + raL;
                    uint32_t ck = (uint32_t)(ks * 2 + akh) ^ (uint32_t)(ra & 7);
                    ldsm4(a[mt], Pb + (uint32_t)(ra * 128) + (ck << 4));
                }
                uint32_t bfr[2][4];
#pragma unroll
                for (int nt2 = 0; nt2 < 2; nt2++) {
                    int rb = n2 + nt2 * 16 + rbL;
                    uint32_t ck = (uint32_t)(ks * 2 + bkh) ^ (uint32_t)(rb & 7);
                    ldsm4(bfr[nt2], Vb + (uint32_t)(rb * 128) + (ck << 4));
                }
#pragma unroll
                for (int mt = 0; mt < 2; mt++)
#pragma unroll
                    for (int nt = 0; nt < 4; nt++)
                        mma16816(acc2[mt][nt], a[mt], &bfr[nt >> 1][(nt & 1) * 2]);
            }
        }
        __syncthreads();

        int nchunk = j + 2;
        if (nchunk < 8) {
            int kt2 = nchunk >> 1, vp2 = nchunk & 1;
            const bf16* base = (vp2 ? vtlo : vthi) + pagebase;
#pragma unroll
            for (int q = 0; q < 4; q++) {
                int idx = q * 256 + tid;
                int r = idx >> 3, c16 = idx & 7;
                cp16(sb + ATT_SV + (j & 1) * 16384 + swz(r * 128 + c16 * 16),
                     base + (size_t)r * 256 + kt2 * 64 + c16 * 8);
            }
            CP_COMMIT();
        }
    }

    // Epilogue: ctx -> cbf (bf16 hi) + c8 ([hi8 | lo8*512])
    const int b = x2 >> 4, head = x2 & 15;
#pragma unroll
    for (int mt = 0; mt < 2; mt++) {
        int r0 = qt * 64 + m2 + mt * 16 + (lane >> 2);
#pragma unroll
        for (int nt = 0; nt < 4; nt++) {
            int colb = h2 * 128 + n2 + nt * 8 + (lane & 3) * 2;
#pragma unroll
            for (int q = 0; q < 2; q++) {
                int r = r0 + q * 8;
                float v0 = acc2[mt][nt][q * 2], v1 = acc2[mt][nt][q * 2 + 1];
                bf16 h0 = __float2bfloat16(v0), h1 = __float2bfloat16(v1);
                float hf0 = __bfloat162float(h0), hf1 = __bfloat162float(h1);
                size_t row = (size_t)(b * 4096 + head * 256 + r);
                *(uint32_t*)(cbf + row * 2048 + colb) = pack2(h0, h1);
                uint16_t hi8 = (uint16_t)e4m3(hf0) | ((uint16_t)e4m3(hf1) << 8);
                uint16_t lo8 = (uint16_t)e4m3(512.f * (v0 - hf0)) |
                               ((uint16_t)e4m3(512.f * (v1 - hf1)) << 8);
                *(uint16_t*)(c8 + row * 4096 + colb) = hi8;
                *(uint16_t*)(c8 + row * 4096 + 2048 + colb) = lo8;
            }
        }
    }
}

// ---------------------------------------------------------------------------
extern "C" void kernel_launch(void* const* d_in, const int* in_sizes, int n_in,
                              void* d_out, int out_size) {
    const float* hidden = (const float*)d_in[0];
    const float* Wq = (const float*)d_in[1];
    const float* bq = (const float*)d_in[2];
    const float* Wk = (const float*)d_in[3];
    const float* bk = (const float*)d_in[4];
    const float* Wv = (const float*)d_in[5];
    const float* bv = (const float*)d_in[6];
    const float* Wo = (const float*)d_in[7];
    const float* bo = (const float*)d_in[8];
    float* out = (float*)d_out;

    bf16 *hbf, *cbf, *wqbf, *wkbf, *wvbf, *wobf;
    unsigned char *h8, *c8, *wq8, *wk8, *wv8, *wo8;
    bf16 *qhi, *qlo, *khi, *klo, *vthi, *vtlo;
    cudaGetSymbolAddress((void**)&hbf, g_hbf);
    cudaGetSymbolAddress((void**)&cbf, g_cbf);
    cudaGetSymbolAddress((void**)&h8, g_h8);
    cudaGetSymbolAddress((void**)&c8, g_c8);
    cudaGetSymbolAddress((void**)&wqbf, g_wqbf);
    cudaGetSymbolAddress((void**)&wkbf, g_wkbf);
    cudaGetSymbolAddress((void**)&wvbf, g_wvbf);
    cudaGetSymbolAddress((void**)&wobf, g_wobf);
    cudaGetSymbolAddress((void**)&wq8, g_wq8);
    cudaGetSymbolAddress((void**)&wk8, g_wk8);
    cudaGetSymbolAddress((void**)&wv8, g_wv8);
    cudaGetSymbolAddress((void**)&wo8, g_wo8);
    cudaGetSymbolAddress((void**)&qhi, g_qhi);
    cudaGetSymbolAddress((void**)&qlo, g_qlo);
    cudaGetSymbolAddress((void**)&khi, g_khi);
    cudaGetSymbolAddress((void**)&klo, g_klo);
    cudaGetSymbolAddress((void**)&vthi, g_vthi);
    cudaGetSymbolAddress((void**)&vtlo, g_vtlo);

    cudaFuncSetAttribute(gemm_qkv, cudaFuncAttributeMaxDynamicSharedMemorySize,
                         GEMM_SMEM);
    cudaFuncSetAttribute(gemm_wo, cudaFuncAttributeMaxDynamicSharedMemorySize,
                         GEMM_SMEM);
    cudaFuncSetAttribute(attn2, cudaFuncAttributeMaxDynamicSharedMemorySize,
                         ATT_SMEM);

    make_wt<<<4096, 256>>>(Wq, wqbf, wq8);
    make_wt<<<4096, 256>>>(Wk, wkbf, wk8);
    make_wt<<<4096, 256>>>(Wv, wvbf, wv8);
    make_wt<<<4096, 256>>>(Wo, wobf, wo8);
    make_act<<<32768, 256>>>(hidden, hbf, h8);

    gemm_qkv<<<dim3(24, 128), 256, GEMM_SMEM>>>(
        hbf, h8, wqbf, wkbf, wvbf, wq8, wk8, wv8, bq, bk, bv,
        qhi, qlo, khi, klo, vthi, vtlo);
    attn2<<<dim3(4, 16, 64), 256, ATT_SMEM>>>(qhi, qlo, khi, klo, vthi, vtlo,
                                              cbf, c8);
    gemm_wo<<<dim3(8, 128), 256, GEMM_SMEM>>>(cbf, c8, wobf, wo8, bo, out);
}

// round 8
// speedup vs baseline: 1.1565x; 1.1565x over previous
#include <cuda_runtime.h>
#include <cuda_bf16.h>
#include <cstdint>

typedef __nv_bfloat16 bf16;

// Problem constants: B=4, S=4096, HID=2048, H=16, P=256, D=128, N=16
#define NELEM 33554432u   // 4*4096*2048
#define KBIG 6144
#define NCHUNK 96         // KBIG / 64
#define MDIM 16384
#define NDIM 2048

// paged bf16 hi/lo buffers: [page=(b*16+head)*16+n][256][128]
__device__ bf16 g_qhi[NELEM];
__device__ bf16 g_qlo[NELEM];
__device__ bf16 g_khi[NELEM];
__device__ bf16 g_klo[NELEM];
__device__ bf16 g_vthi[NELEM];  // transposed: [page][d2:128][p2:256]
__device__ bf16 g_vtlo[NELEM];

__device__ bf16 g_hbig[(size_t)MDIM * KBIG];   // hidden: [hi,hi,lo]
__device__ bf16 g_cbig[(size_t)MDIM * KBIG];   // ctx:    [hi,hi,lo]
__device__ bf16 g_wq[(size_t)NDIM * KBIG];     // W: [hi,lo,hi]
__device__ bf16 g_wk[(size_t)NDIM * KBIG];
__device__ bf16 g_wv[(size_t)NDIM * KBIG];
__device__ bf16 g_wo[(size_t)NDIM * KBIG];

// ---------------------------------------------------------------------------
// helpers
// ---------------------------------------------------------------------------
__device__ __forceinline__ uint32_t smem_u32(const void* p) {
    uint32_t a;
    asm("{ .reg .u64 t; cvta.to.shared.u64 t, %1; cvt.u32.u64 %0, t; }"
        : "=r"(a) : "l"(p));
    return a;
}
__device__ __forceinline__ void cp16(uint32_t sa, const void* g) {
    asm volatile("cp.async.cg.shared.global [%0], [%1], 16;" :: "r"(sa), "l"(g));
}
#define CP_COMMIT() asm volatile("cp.async.commit_group;" ::: "memory")

__device__ __forceinline__ void ldsm4(uint32_t* r, uint32_t addr) {
    asm volatile("ldmatrix.sync.aligned.m8n8.x4.shared.b16 {%0,%1,%2,%3}, [%4];"
                 : "=r"(r[0]), "=r"(r[1]), "=r"(r[2]), "=r"(r[3]) : "r"(addr));
}
__device__ __forceinline__ void mma16816(float* c, const uint32_t* a,
                                         const uint32_t* b) {
    asm volatile(
        "mma.sync.aligned.m16n8k16.row.col.f32.bf16.bf16.f32 "
        "{%0,%1,%2,%3}, {%4,%5,%6,%7}, {%8,%9}, {%0,%1,%2,%3};"
        : "+f"(c[0]), "+f"(c[1]), "+f"(c[2]), "+f"(c[3])
        : "r"(a[0]), "r"(a[1]), "r"(a[2]), "r"(a[3]), "r"(b[0]), "r"(b[1]));
}
__device__ __forceinline__ uint32_t swz(uint32_t o) { return o ^ ((o >> 3) & 0x70); }
__device__ __forceinline__ uint32_t pack2(bf16 a, bf16 b) {
    return (uint32_t)*(uint16_t*)&a | ((uint32_t)*(uint16_t*)&b << 16);
}

// ---------------------------------------------------------------------------
// fp32 -> split-bf16 buffers. mode=0 (activation): [hi, hi, lo]
// mode=1 (weight): [hi, lo, hi].
// ---------------------------------------------------------------------------
__global__ __launch_bounds__(256)
void make_big(const float* __restrict__ src, bf16* __restrict__ dst, int mode) {
    size_t t = (size_t)blockIdx.x * 256 + threadIdx.x;
    size_t row = t >> 9;
    int col = (int)(t & 511) << 2;
    float4 x = *(const float4*)(src + row * 2048 + col);
    bf16 h[4], l[4];
    float xs[4] = {x.x, x.y, x.z, x.w};
#pragma unroll
    for (int i = 0; i < 4; i++) {
        h[i] = __float2bfloat16(xs[i]);
        l[i] = __float2bfloat16(xs[i] - __bfloat162float(h[i]));
    }
    bf16* d0 = dst + row * KBIG + col;
    uint32_t hp0 = pack2(h[0], h[1]), hp1 = pack2(h[2], h[3]);
    uint32_t lp0 = pack2(l[0], l[1]), lp1 = pack2(l[2], l[3]);
    ((uint32_t*)d0)[0] = hp0; ((uint32_t*)d0)[1] = hp1;
    if (mode == 0) {
        ((uint32_t*)(d0 + 2048))[0] = hp0; ((uint32_t*)(d0 + 2048))[1] = hp1;
        ((uint32_t*)(d0 + 4096))[0] = lp0; ((uint32_t*)(d0 + 4096))[1] = lp1;
    } else {
        ((uint32_t*)(d0 + 2048))[0] = lp0; ((uint32_t*)(d0 + 2048))[1] = lp1;
        ((uint32_t*)(d0 + 4096))[0] = hp0; ((uint32_t*)(d0 + 4096))[1] = hp1;
    }
}

// ---------------------------------------------------------------------------
// GEMM mainloop: 128m x 128n block tile, 2 CTAs/SM (96KB smem each),
// K=6144 in 96 chunks of 64, 3-stage cp.async ring, single sync per chunk.
// 8 warps as 2m x 4n, warp tile 64x32 (acc 64 regs -> fits 128-reg cap).
// ---------------------------------------------------------------------------
#define NSTG 3
#define STG_BYTES 32768   // A 16KB + B 16KB
#define GEMM_SMEM (NSTG * STG_BYTES)

__device__ __forceinline__ void load_chunk(
    const bf16* __restrict__ A, const bf16* __restrict__ W,
    uint32_t stg, int bm, int bn, int chunk, int tid) {
#pragma unroll
    for (int j = 0; j < 8; j++) {
        int idx = j * 256 + tid;          // 0..2047
        bool isB = idx >= 1024;
        int r = (idx & 1023) >> 3;        // 0..127
        int c16 = idx & 7;
        const bf16* src =
            (isB ? W + (size_t)(bn + r) * KBIG : A + (size_t)(bm + r) * KBIG)
            + chunk * 64 + c16 * 8;
        uint32_t off = swz((uint32_t)(r * 128 + c16 * 16));
        cp16(stg + (isB ? 16384 : 0) + off, src);
    }
    CP_COMMIT();
}

__device__ __forceinline__ void gemm_mainloop(
    const bf16* __restrict__ A, const bf16* __restrict__ W,
    uint32_t data, int bm, int bn, float (&acc)[4][4][4],
    int tid, int wid, int lane) {
    const int m_base = (wid & 1) * 64;
    const int n_base = (wid >> 1) * 32;

    // Prologue: chunks 0,1 -> stages 0,1
    load_chunk(A, W, data, bm, bn, 0, tid);
    load_chunk(A, W, data + STG_BYTES, bm, bn, 1, tid);

    const int raL = lane & 15;
    const int akh = lane >> 4;
    const int rbL = (lane & 7) + ((lane & 16) >> 1);
    const int bkh = (lane >> 3) & 1;

    int stg_i = 0;   // stage of chunk i
    for (int i = 0; i < NCHUNK; i++) {
        if (i < NCHUNK - 1)
            asm volatile("cp.async.wait_group 1;" ::: "memory");
        else
            asm volatile("cp.async.wait_group 0;" ::: "memory");
        __syncthreads();

        // prefetch chunk i+2 into stage (i+2)%3 == (i-1)%3 (freed at i-1)
        int nc = i + 2;
        int stg_n = stg_i + 2; if (stg_n >= NSTG) stg_n -= NSTG;
        if (nc < NCHUNK)
            load_chunk(A, W, data + stg_n * STG_BYTES, bm, bn, nc, tid);

        uint32_t sA = data + stg_i * STG_BYTES;
        uint32_t sB = sA + 16384;

#pragma unroll
        for (int ks = 0; ks < 4; ks++) {
            uint32_t a[4][4];
#pragma unroll
            for (int mt = 0; mt < 4; mt++) {
                int ra = m_base + mt * 16 + raL;
                uint32_t ck = (uint32_t)(ks * 2 + akh) ^ (uint32_t)(ra & 7);
                ldsm4(a[mt], sA + (uint32_t)(ra * 128) + (ck << 4));
            }
            uint32_t b[2][4];
#pragma unroll
            for (int nt2 = 0; nt2 < 2; nt2++) {
                int rb = n_base + nt2 * 16 + rbL;
                uint32_t ck = (uint32_t)(ks * 2 + bkh) ^ (uint32_t)(rb & 7);
                ldsm4(b[nt2], sB + (uint32_t)(rb * 128) + (ck << 4));
            }
#pragma unroll
            for (int mt = 0; mt < 4; mt++)
#pragma unroll
                for (int nt = 0; nt < 4; nt++)
                    mma16816(acc[mt][nt], a[mt], &b[nt >> 1][(nt & 1) * 2]);
        }
        if (++stg_i == NSTG) stg_i = 0;
    }
    __syncthreads();  // protect smem before epilogue reuse
}

// ---------------------------------------------------------------------------
// Merged QKV GEMM. grid (48, 128): wsel = x>>4, bn=(x&15)*128 (one head).
// ---------------------------------------------------------------------------
__global__ __launch_bounds__(256, 2)
void gemm_qkv(const bf16* __restrict__ A,
              const bf16* __restrict__ W0, const bf16* __restrict__ W1,
              const bf16* __restrict__ W2,
              const float* __restrict__ b0, const float* __restrict__ b1,
              const float* __restrict__ b2,
              bf16* __restrict__ qhi, bf16* __restrict__ qlo,
              bf16* __restrict__ khi, bf16* __restrict__ klo,
              bf16* __restrict__ vthi, bf16* __restrict__ vtlo) {
    extern __shared__ char dsm[];
    const uint32_t data = smem_u32(dsm);
    const int tid = threadIdx.x, wid = tid >> 5, lane = tid & 31;
    const int wsel = blockIdx.x >> 4;
    const int bn = (blockIdx.x & 15) << 7;
    const int bm = blockIdx.y << 7;
    const bf16* W = wsel == 0 ? W0 : wsel == 1 ? W1 : W2;
    const float* bias = wsel == 0 ? b0 : wsel == 1 ? b1 : b2;

    float acc[4][4][4];
#pragma unroll
    for (int mt = 0; mt < 4; mt++)
#pragma unroll
        for (int nt = 0; nt < 4; nt++)
#pragma unroll
            for (int r = 0; r < 4; r++) acc[mt][nt][r] = 0.f;

    gemm_mainloop(A, W, data, bm, bn, acc, tid, wid, lane);

    const int m_base = (wid & 1) * 64;
    const int n_base = (wid >> 1) * 32;

    // bias add
#pragma unroll
    for (int mt = 0; mt < 4; mt++)
#pragma unroll
        for (int nt = 0; nt < 4; nt++) {
            int col = bn + n_base + nt * 8 + (lane & 3) * 2;
            float bb0 = bias[col], bb1 = bias[col + 1];
            acc[mt][nt][0] += bb0; acc[mt][nt][1] += bb1;
            acc[mt][nt][2] += bb0; acc[mt][nt][3] += bb1;
        }

    const int b = bm >> 12, s0 = bm & 4095;
    const int page = s0 >> 8, par = (s0 >> 7) & 1;
    const int head = bn >> 7;
    size_t pb = ((size_t)((b * 16 + head) * 16 + page)) << 15;

    if (wsel < 2) {
        bf16* dhi = wsel ? khi : qhi;
        bf16* dlo = wsel ? klo : qlo;
        float* smf = (float*)dsm;  // [c:128][r:132]
#pragma unroll
        for (int mt = 0; mt < 4; mt++) {
            int r = m_base + mt * 16 + (lane >> 2);
#pragma unroll
            for (int nt = 0; nt < 4; nt++) {
                int c = n_base + nt * 8 + (lane & 3) * 2;
                smf[c * 132 + r] = acc[mt][nt][0];
                smf[(c + 1) * 132 + r] = acc[mt][nt][1];
                smf[c * 132 + r + 8] = acc[mt][nt][2];
                smf[(c + 1) * 132 + r + 8] = acc[mt][nt][3];
            }
        }
        __syncthreads();
        for (int cc = wid; cc < 128; cc += 8) {
            float4 v = *(const float4*)&smf[cc * 132 + lane * 4];
            bf16 h0 = __float2bfloat16(v.x), h1 = __float2bfloat16(v.y);
            bf16 h2 = __float2bfloat16(v.z), h3 = __float2bfloat16(v.w);
            bf16 l0 = __float2bfloat16(v.x - __bfloat162float(h0));
            bf16 l1 = __float2bfloat16(v.y - __bfloat162float(h1));
            bf16 l2 = __float2bfloat16(v.z - __bfloat162float(h2));
            bf16 l3 = __float2bfloat16(v.w - __bfloat162float(h3));
            size_t off = pb + (size_t)(2 * cc + par) * 128 + lane * 4;
            *(uint2*)(dhi + off) = make_uint2(pack2(h0, h1), pack2(h2, h3));
            *(uint2*)(dlo + off) = make_uint2(pack2(l0, l1), pack2(l2, l3));
        }
    } else {
        // V: transposed paged store [page][d2=s&127][p2=2*dim+par]
#pragma unroll
        for (int nt = 0; nt < 4; nt++) {
            int cw = n_base + nt * 8 + (lane & 3) * 2;  // dim within head
#pragma unroll
            for (int mt = 0; mt < 4; mt++) {
                int r0 = m_base + mt * 16 + (lane >> 2);
#pragma unroll
                for (int q = 0; q < 2; q++) {
                    int r = r0 + q * 8;
#pragma unroll
                    for (int e = 0; e < 2; e++) {
                        float v = acc[mt][nt][q * 2 + e];
                        bf16 h = __float2bfloat16(v);
                        bf16 l = __float2bfloat16(v - __bfloat162float(h));
                        size_t off = pb + (size_t)r * 256 + 2 * (cw + e) + par;
                        vthi[off] = h;
                        vtlo[off] = l;
                    }
                }
            }
        }
    }
}

// ---------------------------------------------------------------------------
// Wo GEMM: plain fp32 output
// ---------------------------------------------------------------------------
__global__ __launch_bounds__(256, 2)
void gemm_wo(const bf16* __restrict__ A, const bf16* __restrict__ W,
             const float* __restrict__ bias, float* __restrict__ C) {
    extern __shared__ char dsm[];
    const uint32_t data = smem_u32(dsm);
    const int tid = threadIdx.x, wid = tid >> 5, lane = tid & 31;
    const int bn = blockIdx.x << 7, bm = blockIdx.y << 7;

    float acc[4][4][4];
#pragma unroll
    for (int mt = 0; mt < 4; mt++)
#pragma unroll
        for (int nt = 0; nt < 4; nt++)
#pragma unroll
            for (int r = 0; r < 4; r++) acc[mt][nt][r] = 0.f;

    gemm_mainloop(A, W, data, bm, bn, acc, tid, wid, lane);

    const int m_base = (wid & 1) * 64;
    const int n_base = (wid >> 1) * 32;
#pragma unroll
    for (int mt = 0; mt < 4; mt++) {
        int r0 = bm + m_base + mt * 16 + (lane >> 2);
#pragma unroll
        for (int nt = 0; nt < 4; nt++) {
            int col = bn + n_base + nt * 8 + (lane & 3) * 2;
            float bb0 = bias[col], bb1 = bias[col + 1];
            float* p0 = C + (size_t)r0 * NDIM + col;
            float* p1 = p0 + (size_t)8 * NDIM;
            *(float2*)p0 = make_float2(acc[mt][nt][0] + bb0, acc[mt][nt][1] + bb1);
            *(float2*)p1 = make_float2(acc[mt][nt][2] + bb0, acc[mt][nt][3] + bb1);
        }
    }
}

// ---------------------------------------------------------------------------
// HMMA attention. Block = (qt 0..3, h2 0..15, x2 0..63), 256 threads.
// ---------------------------------------------------------------------------
#define ATT_SQ 0
#define ATT_SK 32768
#define ATT_SP 32768
#define ATT_SV 98304
#define ATT_SS 163840
#define ATT_SMEM 230400
#define SST 260

__global__ __launch_bounds__(256, 1)
void attn2(const bf16* __restrict__ qhi, const bf16* __restrict__ qlo,
           const bf16* __restrict__ khi, const bf16* __restrict__ klo,
           const bf16* __restrict__ vthi, const bf16* __restrict__ vtlo,
           bf16* __restrict__ cbig) {
    extern __shared__ char smraw[];
    const uint32_t sb = smem_u32(smraw);
    float* sS = (float*)(smraw + ATT_SS);

    const float SCALE = 0.08838834764831843f;
    const int qt = blockIdx.x, h2 = blockIdx.y, x2 = blockIdx.z;
    const int tid = threadIdx.x, wid = tid >> 5, lane = tid & 31;
    const size_t pagebase = ((size_t)(x2 * 16 + h2)) << 15;

    const int raL = lane & 15, akh = lane >> 4;
    const int rbL = (lane & 7) + ((lane & 16) >> 1), bkh = (lane >> 3) & 1;

    // Phase 1 loads: Q (64 rows) + K (256 rows), hi & lo
#pragma unroll
    for (int q = 0; q < 8; q++) {
        int idx = q * 256 + tid;
        int prec = idx >> 10, rem = idx & 1023;
        int r = rem >> 4, kc = (rem >> 3) & 1, c16 = rem & 7;
        const bf16* s = (prec ? qlo : qhi) + pagebase +
                        (size_t)(qt * 64 + r) * 128 + kc * 64 + c16 * 8;
        cp16(sb + ATT_SQ + prec * 16384 + kc * 8192 + swz(r * 128 + c16 * 16), s);
    }
#pragma unroll
    for (int q = 0; q < 32; q++) {
        int idx = q * 256 + tid;
        int prec = idx >> 12, rem = idx & 4095;
        int r = rem >> 4, kc = (rem >> 3) & 1, c16 = rem & 7;
        const bf16* s = (prec ? klo : khi) + pagebase + (size_t)r * 128 +
                        kc * 64 + c16 * 8;
        cp16(sb + ATT_SK + prec * 65536 + kc * 32768 + swz(r * 128 + c16 * 16), s);
    }
    CP_COMMIT();
    asm volatile("cp.async.wait_group 0;" ::: "memory");
    __syncthreads();

    // QK: S[64][256] = 3-term split. warp tile 32m x 64n
    {
        const int m_base = (wid & 1) * 32;
        const int n_base = (wid >> 1) * 64;
        float acc[2][8][4];
#pragma unroll
        for (int mt = 0; mt < 2; mt++)
#pragma unroll
            for (int nt = 0; nt < 8; nt++)
#pragma unroll
                for (int r = 0; r < 4; r++) acc[mt][nt][r] = 0.f;

        const int ap[3] = {0, 0, 1}, bp[3] = {0, 1, 0};
#pragma unroll 1
        for (int t = 0; t < 3; t++) {
            uint32_t Ab = sb + ATT_SQ + ap[t] * 16384;
            uint32_t Bb = sb + ATT_SK + bp[t] * 65536;
#pragma unroll
            for (int kc = 0; kc < 2; kc++) {
#pragma unroll
                for (int ks = 0; ks < 4; ks++) {
                    uint32_t a[2][4];
#pragma unroll
                    for (int mt = 0; mt < 2; mt++) {
                        int ra = m_base + mt * 16 + raL;
                        uint32_t ck = (uint32_t)(ks * 2 + akh) ^ (uint32_t)(ra & 7);
                        ldsm4(a[mt], Ab + kc * 8192 + (uint32_t)(ra * 128) + (ck << 4));
                    }
                    uint32_t bfr[4][4];
#pragma unroll
                    for (int nt2 = 0; nt2 < 4; nt2++) {
                        int rb = n_base + nt2 * 16 + rbL;
                        uint32_t ck = (uint32_t)(ks * 2 + bkh) ^ (uint32_t)(rb & 7);
                        ldsm4(bfr[nt2], Bb + kc * 32768 + (uint32_t)(rb * 128) + (ck << 4));
                    }
#pragma unroll
                    for (int mt = 0; mt < 2; mt++)
#pragma unroll
                        for (int nt = 0; nt < 8; nt++)
                            mma16816(acc[mt][nt], a[mt], &bfr[nt >> 1][(nt & 1) * 2]);
                }
            }
        }
#pragma unroll
        for (int mt = 0; mt < 2; mt++) {
            int r = m_base + mt * 16 + (lane >> 2);
#pragma unroll
            for (int nt = 0; nt < 8; nt++) {
                int c = n_base + nt * 8 + (lane & 3) * 2;
                sS[r * SST + c] = acc[mt][nt][0] * SCALE;
                sS[r * SST + c + 1] = acc[mt][nt][1] * SCALE;
                sS[(r + 8) * SST + c] = acc[mt][nt][2] * SCALE;
                sS[(r + 8) * SST + c + 1] = acc[mt][nt][3] * SCALE;
            }
        }
    }
    __syncthreads();

    // prefetch V chunks 0 (Vhi kt0) and 1 (Vlo kt0)
#pragma unroll
    for (int cch = 0; cch < 2; cch++) {
        const bf16* base = (cch ? vtlo : vthi) + pagebase;
#pragma unroll
        for (int q = 0; q < 4; q++) {
            int idx = q * 256 + tid;
            int r = idx >> 3, c16 = idx & 7;
            cp16(sb + ATT_SV + cch * 16384 + swz(r * 128 + c16 * 16),
                 base + (size_t)r * 256 + 0 * 64 + c16 * 8);
        }
        CP_COMMIT();
    }

    // softmax: warp per row
    for (int r = wid; r < 64; r += 8) {
        float v[8];
        float m = -3.4e38f;
#pragma unroll
        for (int c = 0; c < 8; c++) {
            v[c] = sS[r * SST + 32 * c + lane];
            m = fmaxf(m, v[c]);
        }
#pragma unroll
        for (int o = 16; o; o >>= 1) m = fmaxf(m, __shfl_xor_sync(0xffffffffu, m, o));
        float sum = 0.f;
#pragma unroll
        for (int c = 0; c < 8; c++) {
            v[c] = __expf(v[c] - m);
            sum += v[c];
        }
#pragma unroll
        for (int o = 16; o; o >>= 1) sum += __shfl_xor_sync(0xffffffffu, sum, o);
        float inv = 1.0f / sum;
#pragma unroll
        for (int c = 0; c < 8; c++) sS[r * SST + 32 * c + lane] = v[c] * inv;
    }
    __syncthreads();

    // P convert: S fp32 -> P hi/lo bf16 sub-tiles [prec][kc4][64][128B]
    {
        int m = tid >> 2, kcq = tid & 3;
        const float* srow = sS + m * SST + kcq * 64;
        uint32_t dh = ATT_SP + kcq * 8192;
#pragma unroll
        for (int j = 0; j < 32; j++) {
            float s0 = srow[2 * j], s1 = srow[2 * j + 1];
            bf16 h0 = __float2bfloat16(s0), h1 = __float2bfloat16(s1);
            bf16 l0 = __float2bfloat16(s0 - __bfloat162float(h0));
            bf16 l1 = __float2bfloat16(s1 - __bfloat162float(h1));
            uint32_t off = swz((uint32_t)(m * 128 + 4 * j));
            *(uint32_t*)(smraw + dh + off) = pack2(h0, h1);
            *(uint32_t*)(smraw + dh + 32768 + off) = pack2(l0, l1);
        }
    }
    __syncthreads();

    // PV: ctx[64][128] = 3-term split, V streamed in 8 chunks.
    float acc2[2][4][4];
#pragma unroll
    for (int mt = 0; mt < 2; mt++)
#pragma unroll
        for (int nt = 0; nt < 4; nt++)
#pragma unroll
            for (int r = 0; r < 4; r++) acc2[mt][nt][r] = 0.f;

    const int m2 = (wid & 1) * 32;
    const int n2 = (wid >> 1) * 32;

#pragma unroll 1
    for (int j = 0; j < 8; j++) {
        int kt = j >> 1, vp = j & 1;
        if (j < 7) asm volatile("cp.async.wait_group 1;" ::: "memory");
        else       asm volatile("cp.async.wait_group 0;" ::: "memory");
        __syncthreads();

        uint32_t Vb = sb + ATT_SV + (j & 1) * 16384;
        int npass = vp ? 1 : 2;
#pragma unroll 1
        for (int p = 0; p < npass; p++) {
            int pp = vp ? 0 : p;
            uint32_t Pb = sb + ATT_SP + pp * 32768 + kt * 8192;
#pragma unroll
            for (int ks = 0; ks < 4; ks++) {
                uint32_t a[2][4];
#pragma unroll
                for (int mt = 0; mt < 2; mt++) {
                    int ra = m2 + mt * 16 + raL;
                    uint32_t ck = (uint32_t)(ks * 2 + akh) ^ (uint32_t)(ra & 7);
                    ldsm4(a[mt], Pb + (uint32_t)(ra * 128) + (ck << 4));
                }
                uint32_t bfr[2][4];
#pragma unroll
                for (int nt2 = 0; nt2 < 2; nt2++) {
                    int rb = n2 + nt2 * 16 + rbL;
                    uint32_t ck = (uint32_t)(ks * 2 + bkh) ^ (uint32_t)(rb & 7);
                    ldsm4(bfr[nt2], Vb + (uint32_t)(rb * 128) + (ck << 4));
                }
#pragma unroll
                for (int mt = 0; mt < 2; mt++)
#pragma unroll
                    for (int nt = 0; nt < 4; nt++)
                        mma16816(acc2[mt][nt], a[mt], &bfr[nt >> 1][(nt & 1) * 2]);
            }
        }
        __syncthreads();

        int nchunk = j + 2;
        if (nchunk < 8) {
            int kt2 = nchunk >> 1, vp2 = nchunk & 1;
            const bf16* base = (vp2 ? vtlo : vthi) + pagebase;
#pragma unroll
            for (int q = 0; q < 4; q++) {
                int idx = q * 256 + tid;
                int r = idx >> 3, c16 = idx & 7;
                cp16(sb + ATT_SV + (j & 1) * 16384 + swz(r * 128 + c16 * 16),
                     base + (size_t)r * 256 + kt2 * 64 + c16 * 8);
            }
            CP_COMMIT();
        }
    }

    // Epilogue: ctx -> cbig [hi, hi, lo]
    const int b = x2 >> 4, head = x2 & 15;
#pragma unroll
    for (int mt = 0; mt < 2; mt++) {
        int r0 = qt * 64 + m2 + mt * 16 + (lane >> 2);
#pragma unroll
        for (int nt = 0; nt < 4; nt++) {
            int colb = h2 * 128 + n2 + nt * 8 + (lane & 3) * 2;
#pragma unroll
            for (int q = 0; q < 2; q++) {
                int r = r0 + q * 8;
                float v0 = acc2[mt][nt][q * 2], v1 = acc2[mt][nt][q * 2 + 1];
                bf16 h0 = __float2bfloat16(v0), h1 = __float2bfloat16(v1);
                bf16 l0 = __float2bfloat16(v0 - __bfloat162float(h0));
                bf16 l1 = __float2bfloat16(v1 - __bfloat162float(h1));
                uint32_t hp = pack2(h0, h1), lp = pack2(l0, l1);
                bf16* d = cbig + (size_t)(b * 4096 + head * 256 + r) * KBIG + colb;
                *(uint32_t*)d = hp;
                *(uint32_t*)(d + 2048) = hp;
                *(uint32_t*)(d + 4096) = lp;
            }
        }
    }
}

// ---------------------------------------------------------------------------
extern "C" void kernel_launch(void* const* d_in, const int* in_sizes, int n_in,
                              void* d_out, int out_size) {
    const float* hidden = (const float*)d_in[0];
    const float* Wq = (const float*)d_in[1];
    const float* bq = (const float*)d_in[2];
    const float* Wk = (const float*)d_in[3];
    const float* bk = (const float*)d_in[4];
    const float* Wv = (const float*)d_in[5];
    const float* bv = (const float*)d_in[6];
    const float* Wo = (const float*)d_in[7];
    const float* bo = (const float*)d_in[8];
    float* out = (float*)d_out;

    bf16 *hbig, *cbig, *wq, *wk, *wv, *wo;
    bf16 *qhi, *qlo, *khi, *klo, *vthi, *vtlo;
    cudaGetSymbolAddress((void**)&hbig, g_hbig);
    cudaGetSymbolAddress((void**)&cbig, g_cbig);
    cudaGetSymbolAddress((void**)&wq, g_wq);
    cudaGetSymbolAddress((void**)&wk, g_wk);
    cudaGetSymbolAddress((void**)&wv, g_wv);
    cudaGetSymbolAddress((void**)&wo, g_wo);
    cudaGetSymbolAddress((void**)&qhi, g_qhi);
    cudaGetSymbolAddress((void**)&qlo, g_qlo);
    cudaGetSymbolAddress((void**)&khi, g_khi);
    cudaGetSymbolAddress((void**)&klo, g_klo);
    cudaGetSymbolAddress((void**)&vthi, g_vthi);
    cudaGetSymbolAddress((void**)&vtlo, g_vtlo);

    cudaFuncSetAttribute(gemm_qkv, cudaFuncAttributeMaxDynamicSharedMemorySize,
                         GEMM_SMEM);
    cudaFuncSetAttribute(gemm_wo, cudaFuncAttributeMaxDynamicSharedMemorySize,
                         GEMM_SMEM);
    cudaFuncSetAttribute(attn2, cudaFuncAttributeMaxDynamicSharedMemorySize,
                         ATT_SMEM);

    make_big<<<4096, 256>>>(Wq, wq, 1);
    make_big<<<4096, 256>>>(Wk, wk, 1);
    make_big<<<4096, 256>>>(Wv, wv, 1);
    make_big<<<4096, 256>>>(Wo, wo, 1);
    make_big<<<32768, 256>>>(hidden, hbig, 0);

    gemm_qkv<<<dim3(48, 128), 256, GEMM_SMEM>>>(
        hbig, wq, wk, wv, bq, bk, bv, qhi, qlo, khi, klo, vthi, vtlo);
    attn2<<<dim3(4, 16, 64), 256, ATT_SMEM>>>(qhi, qlo, khi, klo, vthi, vtlo, cbig);
    gemm_wo<<<dim3(16, 128), 256, GEMM_SMEM>>>(cbig, wo, bo, out);
}

// round 9
// speedup vs baseline: 1.2154x; 1.0509x over previous
#include <cuda_runtime.h>
#include <cuda_bf16.h>
#include <cstdint>

typedef __nv_bfloat16 bf16;

// Problem constants: B=4, S=4096, HID=2048, H=16, P=256, D=128, N=16
// Key-axis permutation: paged row index p2' = par*128 + dim (was 2*dim+par).
// Applied consistently to K rows, Q rows, V columns, and attn output remap.
#define NELEM 33554432u   // 4*4096*2048
#define NCHUNK 96
#define MDIM 16384
#define NDIM 2048

// paged bf16 hi/lo buffers: [page=(b*16+head)*16+n][256][128]
__device__ bf16 g_qhi[NELEM];
__device__ bf16 g_qlo[NELEM];
__device__ bf16 g_khi[NELEM];
__device__ bf16 g_klo[NELEM];
__device__ bf16 g_vthi[NELEM];  // transposed: [page][d2:128][p2':256]
__device__ bf16 g_vtlo[NELEM];

// compact split layout: [rows][4096] = [hi(2048) | lo(2048)]
__device__ bf16 g_hbig[(size_t)MDIM * 4096];
__device__ bf16 g_cbig[(size_t)MDIM * 4096];
__device__ bf16 g_wq[(size_t)NDIM * 4096];
__device__ bf16 g_wk[(size_t)NDIM * 4096];
__device__ bf16 g_wv[(size_t)NDIM * 4096];
__device__ bf16 g_wo[(size_t)NDIM * 4096];

// ---------------------------------------------------------------------------
// helpers
// ---------------------------------------------------------------------------
__device__ __forceinline__ uint32_t smem_u32(const void* p) {
    uint32_t a;
    asm("{ .reg .u64 t; cvta.to.shared.u64 t, %1; cvt.u32.u64 %0, t; }"
        : "=r"(a) : "l"(p));
    return a;
}
__device__ __forceinline__ void cp16(uint32_t sa, const void* g) {
    asm volatile("cp.async.cg.shared.global [%0], [%1], 16;" :: "r"(sa), "l"(g));
}
#define CP_COMMIT() asm volatile("cp.async.commit_group;" ::: "memory")

__device__ __forceinline__ void ldsm4(uint32_t* r, uint32_t addr) {
    asm volatile("ldmatrix.sync.aligned.m8n8.x4.shared.b16 {%0,%1,%2,%3}, [%4];"
                 : "=r"(r[0]), "=r"(r[1]), "=r"(r[2]), "=r"(r[3]) : "r"(addr));
}
__device__ __forceinline__ void mma16816(float* c, const uint32_t* a,
                                         const uint32_t* b) {
    asm volatile(
        "mma.sync.aligned.m16n8k16.row.col.f32.bf16.bf16.f32 "
        "{%0,%1,%2,%3}, {%4,%5,%6,%7}, {%8,%9}, {%0,%1,%2,%3};"
        : "+f"(c[0]), "+f"(c[1]), "+f"(c[2]), "+f"(c[3])
        : "r"(a[0]), "r"(a[1]), "r"(a[2]), "r"(a[3]), "r"(b[0]), "r"(b[1]));
}
__device__ __forceinline__ uint32_t swz(uint32_t o) { return o ^ ((o >> 3) & 0x70); }
__device__ __forceinline__ uint32_t pack2(bf16 a, bf16 b) {
    return (uint32_t)*(uint16_t*)&a | ((uint32_t)*(uint16_t*)&b << 16);
}

// ---------------------------------------------------------------------------
// fp32 -> compact split-bf16 [hi | lo]
// ---------------------------------------------------------------------------
__device__ __forceinline__ void split_one(const float* __restrict__ src,
                                          bf16* __restrict__ dst, size_t t) {
    size_t row = t >> 9;
    int col = (int)(t & 511) << 2;
    float4 x = *(const float4*)(src + row * 2048 + col);
    bf16 h[4], l[4];
    float xs[4] = {x.x, x.y, x.z, x.w};
#pragma unroll
    for (int i = 0; i < 4; i++) {
        h[i] = __float2bfloat16(xs[i]);
        l[i] = __float2bfloat16(xs[i] - __bfloat162float(h[i]));
    }
    bf16* d0 = dst + row * 4096 + col;
    ((uint32_t*)d0)[0] = pack2(h[0], h[1]);
    ((uint32_t*)d0)[1] = pack2(h[2], h[3]);
    ((uint32_t*)(d0 + 2048))[0] = pack2(l[0], l[1]);
    ((uint32_t*)(d0 + 2048))[1] = pack2(l[2], l[3]);
}

__global__ __launch_bounds__(256)
void make_split(const float* __restrict__ src, bf16* __restrict__ dst) {
    split_one(src, dst, (size_t)blockIdx.x * 256 + threadIdx.x);
}

__global__ __launch_bounds__(256)
void make_split4(const float* __restrict__ s0, bf16* __restrict__ d0,
                 const float* __restrict__ s1, bf16* __restrict__ d1,
                 const float* __restrict__ s2, bf16* __restrict__ d2,
                 const float* __restrict__ s3, bf16* __restrict__ d3) {
    const float* s = blockIdx.y == 0 ? s0 : blockIdx.y == 1 ? s1
                     : blockIdx.y == 2 ? s2 : s3;
    bf16* d = blockIdx.y == 0 ? d0 : blockIdx.y == 1 ? d1
              : blockIdx.y == 2 ? d2 : d3;
    split_one(s, d, (size_t)blockIdx.x * 256 + threadIdx.x);
}

// ---------------------------------------------------------------------------
// GEMM mainloop: 128m x 128n block, 2 CTAs/SM, K effective 6144 in 96 chunks
// of 64 with chunk->source remap into compact [hi|lo] operands:
//   chunk i: A col = (i<32 ? i : i-32)*64,  W col = (i<64 ? i : i-64)*64
// giving Ahi*Whi (i<32) + Ahi*Wlo (32..63) + Alo*Whi (64..95).
// 3-stage cp.async ring, single sync per chunk. 8 warps as 2m x 4n (64x32).
// ---------------------------------------------------------------------------
#define NSTG 3
#define STG_BYTES 32768   // A 16KB + B 16KB
#define GEMM_SMEM (NSTG * STG_BYTES)

__device__ __forceinline__ void load_chunk(
    const bf16* __restrict__ A, const bf16* __restrict__ W,
    uint32_t stg, int bm, int bn, int chunk, int tid) {
    int acol = chunk < 32 ? chunk : chunk - 32;
    int wcol = chunk < 64 ? chunk : chunk - 64;
#pragma unroll
    for (int j = 0; j < 8; j++) {
        int idx = j * 256 + tid;          // 0..2047
        bool isB = idx >= 1024;
        int r = (idx & 1023) >> 3;        // 0..127
        int c16 = idx & 7;
        const bf16* src = isB
            ? W + (size_t)(bn + r) * 4096 + wcol * 64 + c16 * 8
            : A + (size_t)(bm + r) * 4096 + acol * 64 + c16 * 8;
        uint32_t off = swz((uint32_t)(r * 128 + c16 * 16));
        cp16(stg + (isB ? 16384 : 0) + off, src);
    }
    CP_COMMIT();
}

__device__ __forceinline__ void gemm_mainloop(
    const bf16* __restrict__ A, const bf16* __restrict__ W,
    uint32_t data, int bm, int bn, float (&acc)[4][4][4],
    int tid, int wid, int lane) {
    const int m_base = (wid & 1) * 64;
    const int n_base = (wid >> 1) * 32;

    load_chunk(A, W, data, bm, bn, 0, tid);
    load_chunk(A, W, data + STG_BYTES, bm, bn, 1, tid);

    const int raL = lane & 15;
    const int akh = lane >> 4;
    const int rbL = (lane & 7) + ((lane & 16) >> 1);
    const int bkh = (lane >> 3) & 1;

    int stg_i = 0;
    for (int i = 0; i < NCHUNK; i++) {
        if (i < NCHUNK - 1)
            asm volatile("cp.async.wait_group 1;" ::: "memory");
        else
            asm volatile("cp.async.wait_group 0;" ::: "memory");
        __syncthreads();

        int nc = i + 2;
        int stg_n = stg_i + 2; if (stg_n >= NSTG) stg_n -= NSTG;
        if (nc < NCHUNK)
            load_chunk(A, W, data + stg_n * STG_BYTES, bm, bn, nc, tid);

        uint32_t sA = data + stg_i * STG_BYTES;
        uint32_t sB = sA + 16384;

#pragma unroll
        for (int ks = 0; ks < 4; ks++) {
            uint32_t a[4][4];
#pragma unroll
            for (int mt = 0; mt < 4; mt++) {
                int ra = m_base + mt * 16 + raL;
                uint32_t ck = (uint32_t)(ks * 2 + akh) ^ (uint32_t)(ra & 7);
                ldsm4(a[mt], sA + (uint32_t)(ra * 128) + (ck << 4));
            }
            uint32_t b[2][4];
#pragma unroll
            for (int nt2 = 0; nt2 < 2; nt2++) {
                int rb = n_base + nt2 * 16 + rbL;
                uint32_t ck = (uint32_t)(ks * 2 + bkh) ^ (uint32_t)(rb & 7);
                ldsm4(b[nt2], sB + (uint32_t)(rb * 128) + (ck << 4));
            }
#pragma unroll
            for (int mt = 0; mt < 4; mt++)
#pragma unroll
                for (int nt = 0; nt < 4; nt++)
                    mma16816(acc[mt][nt], a[mt], &b[nt >> 1][(nt & 1) * 2]);
        }
        if (++stg_i == NSTG) stg_i = 0;
    }
    __syncthreads();
}

// ---------------------------------------------------------------------------
// Merged QKV GEMM. grid (48, 128): wsel = x>>4, bn=(x&15)*128 (one head).
// Q/K rows use permuted index p2' = par*128 + dim. V columns likewise.
// ---------------------------------------------------------------------------
__global__ __launch_bounds__(256, 2)
void gemm_qkv(const bf16* __restrict__ A,
              const bf16* __restrict__ W0, const bf16* __restrict__ W1,
              const bf16* __restrict__ W2,
              const float* __restrict__ b0, const float* __restrict__ b1,
              const float* __restrict__ b2,
              bf16* __restrict__ qhi, bf16* __restrict__ qlo,
              bf16* __restrict__ khi, bf16* __restrict__ klo,
              bf16* __restrict__ vthi, bf16* __restrict__ vtlo) {
    extern __shared__ char dsm[];
    const uint32_t data = smem_u32(dsm);
    const int tid = threadIdx.x, wid = tid >> 5, lane = tid & 31;
    const int wsel = blockIdx.x >> 4;
    const int bn = (blockIdx.x & 15) << 7;
    const int bm = blockIdx.y << 7;
    const bf16* W = wsel == 0 ? W0 : wsel == 1 ? W1 : W2;
    const float* bias = wsel == 0 ? b0 : wsel == 1 ? b1 : b2;

    float acc[4][4][4];
#pragma unroll
    for (int mt = 0; mt < 4; mt++)
#pragma unroll
        for (int nt = 0; nt < 4; nt++)
#pragma unroll
            for (int r = 0; r < 4; r++) acc[mt][nt][r] = 0.f;

    gemm_mainloop(A, W, data, bm, bn, acc, tid, wid, lane);

    const int m_base = (wid & 1) * 64;
    const int n_base = (wid >> 1) * 32;

#pragma unroll
    for (int mt = 0; mt < 4; mt++)
#pragma unroll
        for (int nt = 0; nt < 4; nt++) {
            int col = bn + n_base + nt * 8 + (lane & 3) * 2;
            float bb0 = bias[col], bb1 = bias[col + 1];
            acc[mt][nt][0] += bb0; acc[mt][nt][1] += bb1;
            acc[mt][nt][2] += bb0; acc[mt][nt][3] += bb1;
        }

    const int b = bm >> 12, s0 = bm & 4095;
    const int page = s0 >> 8, par = (s0 >> 7) & 1;
    const int head = bn >> 7;
    size_t pb = ((size_t)((b * 16 + head) * 16 + page)) << 15;

    if (wsel < 2) {
        bf16* dhi = wsel ? khi : qhi;
        bf16* dlo = wsel ? klo : qlo;
        float* smf = (float*)dsm;  // [c:128][r:132]
#pragma unroll
        for (int mt = 0; mt < 4; mt++) {
            int r = m_base + mt * 16 + (lane >> 2);
#pragma unroll
            for (int nt = 0; nt < 4; nt++) {
                int c = n_base + nt * 8 + (lane & 3) * 2;
                smf[c * 132 + r] = acc[mt][nt][0];
                smf[(c + 1) * 132 + r] = acc[mt][nt][1];
                smf[c * 132 + r + 8] = acc[mt][nt][2];
                smf[(c + 1) * 132 + r + 8] = acc[mt][nt][3];
            }
        }
        __syncthreads();
        for (int cc = wid; cc < 128; cc += 8) {
            float4 v = *(const float4*)&smf[cc * 132 + lane * 4];
            bf16 h0 = __float2bfloat16(v.x), h1 = __float2bfloat16(v.y);
            bf16 h2 = __float2bfloat16(v.z), h3 = __float2bfloat16(v.w);
            bf16 l0 = __float2bfloat16(v.x - __bfloat162float(h0));
            bf16 l1 = __float2bfloat16(v.y - __bfloat162float(h1));
            bf16 l2 = __float2bfloat16(v.z - __bfloat162float(h2));
            bf16 l3 = __float2bfloat16(v.w - __bfloat162float(h3));
            // permuted row p2' = par*128 + cc
            size_t off = pb + (size_t)(par * 128 + cc) * 128 + lane * 4;
            *(uint2*)(dhi + off) = make_uint2(pack2(h0, h1), pack2(h2, h3));
            *(uint2*)(dlo + off) = make_uint2(pack2(l0, l1), pack2(l2, l3));
        }
    } else {
        // V: transposed paged store [page][d2=r][p2'=par*128+dim] — paired u32
#pragma unroll
        for (int nt = 0; nt < 4; nt++) {
            int cw = n_base + nt * 8 + (lane & 3) * 2;  // dim within head
#pragma unroll
            for (int mt = 0; mt < 4; mt++) {
                int r0 = m_base + mt * 16 + (lane >> 2);
#pragma unroll
                for (int q = 0; q < 2; q++) {
                    int r = r0 + q * 8;
                    float v0 = acc[mt][nt][q * 2], v1 = acc[mt][nt][q * 2 + 1];
                    bf16 h0 = __float2bfloat16(v0), h1 = __float2bfloat16(v1);
                    bf16 l0 = __float2bfloat16(v0 - __bfloat162float(h0));
                    bf16 l1 = __float2bfloat16(v1 - __bfloat162float(h1));
                    size_t off = pb + (size_t)r * 256 + par * 128 + cw;
                    *(uint32_t*)(vthi + off) = pack2(h0, h1);
                    *(uint32_t*)(vtlo + off) = pack2(l0, l1);
                }
            }
        }
    }
}

// ---------------------------------------------------------------------------
// Wo GEMM: plain fp32 output
// ---------------------------------------------------------------------------
__global__ __launch_bounds__(256, 2)
void gemm_wo(const bf16* __restrict__ A, const bf16* __restrict__ W,
             const float* __restrict__ bias, float* __restrict__ C) {
    extern __shared__ char dsm[];
    const uint32_t data = smem_u32(dsm);
    const int tid = threadIdx.x, wid = tid >> 5, lane = tid & 31;
    const int bn = blockIdx.x << 7, bm = blockIdx.y << 7;

    float acc[4][4][4];
#pragma unroll
    for (int mt = 0; mt < 4; mt++)
#pragma unroll
        for (int nt = 0; nt < 4; nt++)
#pragma unroll
            for (int r = 0; r < 4; r++) acc[mt][nt][r] = 0.f;

    gemm_mainloop(A, W, data, bm, bn, acc, tid, wid, lane);

    const int m_base = (wid & 1) * 64;
    const int n_base = (wid >> 1) * 32;
#pragma unroll
    for (int mt = 0; mt < 4; mt++) {
        int r0 = bm + m_base + mt * 16 + (lane >> 2);
#pragma unroll
        for (int nt = 0; nt < 4; nt++) {
            int col = bn + n_base + nt * 8 + (lane & 3) * 2;
            float bb0 = bias[col], bb1 = bias[col + 1];
            float* p0 = C + (size_t)r0 * NDIM + col;
            float* p1 = p0 + (size_t)8 * NDIM;
            *(float2*)p0 = make_float2(acc[mt][nt][0] + bb0, acc[mt][nt][1] + bb1);
            *(float2*)p1 = make_float2(acc[mt][nt][2] + bb0, acc[mt][nt][3] + bb1);
        }
    }
}

// ---------------------------------------------------------------------------
// HMMA attention. Block = (qt 0..3, h2 0..15, x2 0..63), 256 threads.
// Rows/cols are in permuted p2' order; output epilogue maps back.
// ---------------------------------------------------------------------------
#define ATT_SQ 0
#define ATT_SK 32768
#define ATT_SP 32768
#define ATT_SV 98304
#define ATT_SS 163840
#define ATT_SMEM 230400
#define SST 260

__global__ __launch_bounds__(256, 1)
void attn2(const bf16* __restrict__ qhi, const bf16* __restrict__ qlo,
           const bf16* __restrict__ khi, const bf16* __restrict__ klo,
           const bf16* __restrict__ vthi, const bf16* __restrict__ vtlo,
           bf16* __restrict__ cbig) {
    extern __shared__ char smraw[];
    const uint32_t sb = smem_u32(smraw);
    float* sS = (float*)(smraw + ATT_SS);

    const float SCALE = 0.08838834764831843f;
    const int qt = blockIdx.x, h2 = blockIdx.y, x2 = blockIdx.z;
    const int tid = threadIdx.x, wid = tid >> 5, lane = tid & 31;
    const size_t pagebase = ((size_t)(x2 * 16 + h2)) << 15;

    const int raL = lane & 15, akh = lane >> 4;
    const int rbL = (lane & 7) + ((lane & 16) >> 1), bkh = (lane >> 3) & 1;

    // Phase 1 loads: Q (64 rows) + K (256 rows), hi & lo
#pragma unroll
    for (int q = 0; q < 8; q++) {
        int idx = q * 256 + tid;
        int prec = idx >> 10, rem = idx & 1023;
        int r = rem >> 4, kc = (rem >> 3) & 1, c16 = rem & 7;
        const bf16* s = (prec ? qlo : qhi) + pagebase +
                        (size_t)(qt * 64 + r) * 128 + kc * 64 + c16 * 8;
        cp16(sb + ATT_SQ + prec * 16384 + kc * 8192 + swz(r * 128 + c16 * 16), s);
    }
#pragma unroll
    for (int q = 0; q < 32; q++) {
        int idx = q * 256 + tid;
        int prec = idx >> 12, rem = idx & 4095;
        int r = rem >> 4, kc = (rem >> 3) & 1, c16 = rem & 7;
        const bf16* s = (prec ? klo : khi) + pagebase + (size_t)r * 128 +
                        kc * 64 + c16 * 8;
        cp16(sb + ATT_SK + prec * 65536 + kc * 32768 + swz(r * 128 + c16 * 16), s);
    }
    CP_COMMIT();
    asm volatile("cp.async.wait_group 0;" ::: "memory");
    __syncthreads();

    // QK: S[64][256] = 3-term split. warp tile 32m x 64n
    {
        const int m_base = (wid & 1) * 32;
        const int n_base = (wid >> 1) * 64;
        float acc[2][8][4];
#pragma unroll
        for (int mt = 0; mt < 2; mt++)
#pragma unroll
            for (int nt = 0; nt < 8; nt++)
#pragma unroll
                for (int r = 0; r < 4; r++) acc[mt][nt][r] = 0.f;

        const int ap[3] = {0, 0, 1}, bp[3] = {0, 1, 0};
#pragma unroll 1
        for (int t = 0; t < 3; t++) {
            uint32_t Ab = sb + ATT_SQ + ap[t] * 16384;
            uint32_t Bb = sb + ATT_SK + bp[t] * 65536;
#pragma unroll
            for (int kc = 0; kc < 2; kc++) {
#pragma unroll
                for (int ks = 0; ks < 4; ks++) {
                    uint32_t a[2][4];
#pragma unroll
                    for (int mt = 0; mt < 2; mt++) {
                        int ra = m_base + mt * 16 + raL;
                        uint32_t ck = (uint32_t)(ks * 2 + akh) ^ (uint32_t)(ra & 7);
                        ldsm4(a[mt], Ab + kc * 8192 + (uint32_t)(ra * 128) + (ck << 4));
                    }
                    uint32_t bfr[4][4];
#pragma unroll
                    for (int nt2 = 0; nt2 < 4; nt2++) {
                        int rb = n_base + nt2 * 16 + rbL;
                        uint32_t ck = (uint32_t)(ks * 2 + bkh) ^ (uint32_t)(rb & 7);
                        ldsm4(bfr[nt2], Bb + kc * 32768 + (uint32_t)(rb * 128) + (ck << 4));
                    }
#pragma unroll
                    for (int mt = 0; mt < 2; mt++)
#pragma unroll
                        for (int nt = 0; nt < 8; nt++)
                            mma16816(acc[mt][nt], a[mt], &bfr[nt >> 1][(nt & 1) * 2]);
                }
            }
        }
#pragma unroll
        for (int mt = 0; mt < 2; mt++) {
            int r = m_base + mt * 16 + (lane >> 2);
#pragma unroll
            for (int nt = 0; nt < 8; nt++) {
                int c = n_base + nt * 8 + (lane & 3) * 2;
                sS[r * SST + c] = acc[mt][nt][0] * SCALE;
                sS[r * SST + c + 1] = acc[mt][nt][1] * SCALE;
                sS[(r + 8) * SST + c] = acc[mt][nt][2] * SCALE;
                sS[(r + 8) * SST + c + 1] = acc[mt][nt][3] * SCALE;
            }
        }
    }
    __syncthreads();

    // prefetch V chunks 0 (Vhi kt0) and 1 (Vlo kt0)
#pragma unroll
    for (int cch = 0; cch < 2; cch++) {
        const bf16* base = (cch ? vtlo : vthi) + pagebase;
#pragma unroll
        for (int q = 0; q < 4; q++) {
            int idx = q * 256 + tid;
            int r = idx >> 3, c16 = idx & 7;
            cp16(sb + ATT_SV + cch * 16384 + swz(r * 128 + c16 * 16),
                 base + (size_t)r * 256 + 0 * 64 + c16 * 8);
        }
        CP_COMMIT();
    }

    // softmax: warp per row
    for (int r = wid; r < 64; r += 8) {
        float v[8];
        float m = -3.4e38f;
#pragma unroll
        for (int c = 0; c < 8; c++) {
            v[c] = sS[r * SST + 32 * c + lane];
            m = fmaxf(m, v[c]);
        }
#pragma unroll
        for (int o = 16; o; o >>= 1) m = fmaxf(m, __shfl_xor_sync(0xffffffffu, m, o));
        float sum = 0.f;
#pragma unroll
        for (int c = 0; c < 8; c++) {
            v[c] = __expf(v[c] - m);
            sum += v[c];
        }
#pragma unroll
        for (int o = 16; o; o >>= 1) sum += __shfl_xor_sync(0xffffffffu, sum, o);
        float inv = 1.0f / sum;
#pragma unroll
        for (int c = 0; c < 8; c++) sS[r * SST + 32 * c + lane] = v[c] * inv;
    }
    __syncthreads();

    // P convert: S fp32 -> P hi/lo bf16 sub-tiles [prec][kc4][64][128B]
    {
        int m = tid >> 2, kcq = tid & 3;
        const float* srow = sS + m * SST + kcq * 64;
        uint32_t dh = ATT_SP + kcq * 8192;
#pragma unroll
        for (int j = 0; j < 32; j++) {
            float s0 = srow[2 * j], s1 = srow[2 * j + 1];
            bf16 h0 = __float2bfloat16(s0), h1 = __float2bfloat16(s1);
            bf16 l0 = __float2bfloat16(s0 - __bfloat162float(h0));
            bf16 l1 = __float2bfloat16(s1 - __bfloat162float(h1));
            uint32_t off = swz((uint32_t)(m * 128 + 4 * j));
            *(uint32_t*)(smraw + dh + off) = pack2(h0, h1);
            *(uint32_t*)(smraw + dh + 32768 + off) = pack2(l0, l1);
        }
    }
    __syncthreads();

    // PV: ctx[64][128] = 3-term split, V streamed in 8 chunks.
    float acc2[2][4][4];
#pragma unroll
    for (int mt = 0; mt < 2; mt++)
#pragma unroll
        for (int nt = 0; nt < 4; nt++)
#pragma unroll
            for (int r = 0; r < 4; r++) acc2[mt][nt][r] = 0.f;

    const int m2 = (wid & 1) * 32;
    const int n2 = (wid >> 1) * 32;

#pragma unroll 1
    for (int j = 0; j < 8; j++) {
        int kt = j >> 1, vp = j & 1;
        if (j < 7) asm volatile("cp.async.wait_group 1;" ::: "memory");
        else       asm volatile("cp.async.wait_group 0;" ::: "memory");
        __syncthreads();

        uint32_t Vb = sb + ATT_SV + (j & 1) * 16384;
        int npass = vp ? 1 : 2;
#pragma unroll 1
        for (int p = 0; p < npass; p++) {
            int pp = vp ? 0 : p;
            uint32_t Pb = sb + ATT_SP + pp * 32768 + kt * 8192;
#pragma unroll
            for (int ks = 0; ks < 4; ks++) {
                uint32_t a[2][4];
#pragma unroll
                for (int mt = 0; mt < 2; mt++) {
                    int ra = m2 + mt * 16 + raL;
                    uint32_t ck = (uint32_t)(ks * 2 + akh) ^ (uint32_t)(ra & 7);
                    ldsm4(a[mt], Pb + (uint32_t)(ra * 128) + (ck << 4));
                }
                uint32_t bfr[2][4];
#pragma unroll
                for (int nt2 = 0; nt2 < 2; nt2++) {
                    int rb = n2 + nt2 * 16 + rbL;
                    uint32_t ck = (uint32_t)(ks * 2 + bkh) ^ (uint32_t)(rb & 7);
                    ldsm4(bfr[nt2], Vb + (uint32_t)(rb * 128) + (ck << 4));
                }
#pragma unroll
                for (int mt = 0; mt < 2; mt++)
#pragma unroll
                    for (int nt = 0; nt < 4; nt++)
                        mma16816(acc2[mt][nt], a[mt], &bfr[nt >> 1][(nt & 1) * 2]);
            }
        }
        __syncthreads();

        int nchunk = j + 2;
        if (nchunk < 8) {
            int kt2 = nchunk >> 1, vp2 = nchunk & 1;
            const bf16* base = (vp2 ? vtlo : vthi) + pagebase;
#pragma unroll
            for (int q = 0; q < 4; q++) {
                int idx = q * 256 + tid;
                int r = idx >> 3, c16 = idx & 7;
                cp16(sb + ATT_SV + (j & 1) * 16384 + swz(r * 128 + c16 * 16),
                     base + (size_t)r * 256 + kt2 * 64 + c16 * 8);
            }
            CP_COMMIT();
        }
    }

    // Epilogue: ctx -> cbig [hi | lo], unpermute query row p2'->p2
    const int b = x2 >> 4, head = x2 & 15;
#pragma unroll
    for (int mt = 0; mt < 2; mt++) {
        int r0 = qt * 64 + m2 + mt * 16 + (lane >> 2);
#pragma unroll
        for (int nt = 0; nt < 4; nt++) {
            int colb = h2 * 128 + n2 + nt * 8 + (lane & 3) * 2;
#pragma unroll
            for (int q = 0; q < 2; q++) {
                int r = r0 + q * 8;                     // permuted p2'
                int p2 = 2 * (r & 127) + (r >> 7);      // original p2
                float v0 = acc2[mt][nt][q * 2], v1 = acc2[mt][nt][q * 2 + 1];
                bf16 h0 = __float2bfloat16(v0), h1 = __float2bfloat16(v1);
                bf16 l0 = __float2bfloat16(v0 - __bfloat162float(h0));
                bf16 l1 = __float2bfloat16(v1 - __bfloat162float(h1));
                bf16* d = cbig + (size_t)(b * 4096 + head * 256 + p2) * 4096 + colb;
                *(uint32_t*)d = pack2(h0, h1);
                *(uint32_t*)(d + 2048) = pack2(l0, l1);
            }
        }
    }
}

// ---------------------------------------------------------------------------
extern "C" void kernel_launch(void* const* d_in, const int* in_sizes, int n_in,
                              void* d_out, int out_size) {
    const float* hidden = (const float*)d_in[0];
    const float* Wq = (const float*)d_in[1];
    const float* bq = (const float*)d_in[2];
    const float* Wk = (const float*)d_in[3];
    const float* bk = (const float*)d_in[4];
    const float* Wv = (const float*)d_in[5];
    const float* bv = (const float*)d_in[6];
    const float* Wo = (const float*)d_in[7];
    const float* bo = (const float*)d_in[8];
    float* out = (float*)d_out;

    bf16 *hbig, *cbig, *wq, *wk, *wv, *wo;
    bf16 *qhi, *qlo, *khi, *klo, *vthi, *vtlo;
    cudaGetSymbolAddress((void**)&hbig, g_hbig);
    cudaGetSymbolAddress((void**)&cbig, g_cbig);
    cudaGetSymbolAddress((void**)&wq, g_wq);
    cudaGetSymbolAddress((void**)&wk, g_wk);
    cudaGetSymbolAddress((void**)&wv, g_wv);
    cudaGetSymbolAddress((void**)&wo, g_wo);
    cudaGetSymbolAddress((void**)&qhi, g_qhi);
    cudaGetSymbolAddress((void**)&qlo, g_qlo);
    cudaGetSymbolAddress((void**)&khi, g_khi);
    cudaGetSymbolAddress((void**)&klo, g_klo);
    cudaGetSymbolAddress((void**)&vthi, g_vthi);
    cudaGetSymbolAddress((void**)&vtlo, g_vtlo);

    cudaFuncSetAttribute(gemm_qkv, cudaFuncAttributeMaxDynamicSharedMemorySize,
                         GEMM_SMEM);
    cudaFuncSetAttribute(gemm_wo, cudaFuncAttributeMaxDynamicSharedMemorySize,
                         GEMM_SMEM);
    cudaFuncSetAttribute(attn2, cudaFuncAttributeMaxDynamicSharedMemorySize,
                         ATT_SMEM);

    make_split4<<<dim3(4096, 4), 256>>>(Wq, wq, Wk, wk, Wv, wv, Wo, wo);
    make_split<<<32768, 256>>>(hidden, hbig);

    gemm_qkv<<<dim3(48, 128), 256, GEMM_SMEM>>>(
        hbig, wq, wk, wv, bq, bk, bv, qhi, qlo, khi, klo, vthi, vtlo);
    attn2<<<dim3(4, 16, 64), 256, ATT_SMEM>>>(qhi, qlo, khi, klo, vthi, vtlo, cbig);
    gemm_wo<<<dim3(16, 128), 256, GEMM_SMEM>>>(cbig, wo, bo, out);
}